// round 1
// baseline (speedup 1.0000x reference)
#include <cuda_runtime.h>
#include <cuda_bf16.h>

#define BATCH 8
#define SEQ   2048
#define DIM   128
#define BQ    32
#define BK    64
#define NT    256
#define QSTR  132   // padded row stride (floats) for Q/K/V tiles
#define PSTR  36    // padded row stride for transposed P tile
#define NEGBIG (-1e30f)

// ---- scratch (no allocations allowed) ----
__device__ float g_partial[BATCH][16][DIM];
__device__ float g_meanv[BATCH][DIM];

// ---- packed f32x2 helpers (FFMA2: rt=1 vs FFMA rt=2 per SMSP) ----
__device__ __forceinline__ unsigned long long ffma2(unsigned long long a,
                                                    unsigned long long b,
                                                    unsigned long long c) {
    unsigned long long d;
    asm("fma.rn.f32x2 %0, %1, %2, %3;" : "=l"(d) : "l"(a), "l"(b), "l"(c));
    return d;
}
__device__ __forceinline__ unsigned long long fmul2(unsigned long long a,
                                                    unsigned long long b) {
    unsigned long long d;
    asm("mul.rn.f32x2 %0, %1, %2;" : "=l"(d) : "l"(a), "l"(b));
    return d;
}
__device__ __forceinline__ unsigned long long pack2(float x) {
    unsigned long long d;
    asm("mov.b64 %0, {%1, %1};" : "=l"(d) : "f"(x));
    return d;
}
__device__ __forceinline__ float2 unpack2(unsigned long long a) {
    float2 f;
    asm("mov.b64 {%0, %1}, %2;" : "=f"(f.x), "=f"(f.y) : "l"(a));
    return f;
}

// ---- mean-of-V: partial sums over 128-row chunks ----
__global__ void meanv_partial_kernel(const float* __restrict__ v) {
    int b = blockIdx.y, c = blockIdx.x, d = threadIdx.x;
    const float* vp = v + ((size_t)b * SEQ + (size_t)c * 128) * DIM + d;
    float s = 0.f;
#pragma unroll 8
    for (int t = 0; t < 128; ++t) s += vp[(size_t)t * DIM];
    g_partial[b][c][d] = s;
}

__global__ void meanv_reduce_kernel() {
    int b = blockIdx.x, d = threadIdx.x;
    float s = 0.f;
#pragma unroll
    for (int c = 0; c < 16; ++c) s += g_partial[b][c][d];
    g_meanv[b][d] = s * (1.0f / SEQ);
}

// ---- flash attention over keys [0, L) ----
__global__ void __launch_bounds__(NT, 2)
attn_kernel(const float* __restrict__ q, const float* __restrict__ k,
            const float* __restrict__ v, const int* __restrict__ elen,
            float* __restrict__ out) {
    extern __shared__ float smem[];
    float* sQ = smem;                    // BQ*QSTR
    float* sK = sQ + BQ * QSTR;          // BK*QSTR
    float* sV = sK + BK * QSTR;          // BK*QSTR
    float* sP = sV + BK * QSTR;          // BK*PSTR, transposed [t][q]
    float* sC = sP + BK * PSTR;          // BQ  (per-row rescale factor)
    float* sL = sC + BQ;                 // BQ  (per-row running denom)

    const int b   = blockIdx.y;
    const int q0  = blockIdx.x * BQ;
    const int L   = elen[b];
    const int tid = threadIdx.x;

    const float* qb = q + (size_t)b * SEQ * DIM;
    const float* kb = k + (size_t)b * SEQ * DIM;
    const float* vb = v + (size_t)b * SEQ * DIM;
    float*       ob = out + (size_t)b * SEQ * DIM;

    if (q0 >= L) {  // whole tile is invalid rows -> uniform softmax -> mean(V)
        for (int idx = tid; idx < BQ * DIM; idx += NT) {
            int r = idx >> 7, d = idx & 127;
            ob[(size_t)(q0 + r) * DIM + d] = g_meanv[b][d];
        }
        return;
    }

    // load Q tile, pre-scaled by 1/sqrt(D)
    const float scale = 0.08838834764831845f;
    for (int idx = tid; idx < BQ * (DIM / 4); idx += NT) {
        int r = idx >> 5, c4 = idx & 31;
        float4 val = ((const float4*)(qb + (size_t)(q0 + r) * DIM))[c4];
        val.x *= scale; val.y *= scale; val.z *= scale; val.w *= scale;
        ((float4*)(sQ + r * QSTR))[c4] = val;
    }

    // phase-1 mapping: ty -> q rows {2ty, 2ty+1}; tx -> k cols {tx+16j}
    const int ty = tid >> 4;
    const int tx = tid & 15;
    // phase-3 mapping: qg -> q rows {4qg..4qg+3}; dg -> d cols {4dg..4dg+3}
    const int qg = tid >> 5;
    const int dg = tid & 31;

    float mrun0 = NEGBIG, mrun1 = NEGBIG;
    float lrun0 = 0.f,    lrun1 = 0.f;
    unsigned long long O2[4][2];
#pragma unroll
    for (int i = 0; i < 4; ++i) { O2[i][0] = 0ull; O2[i][1] = 0ull; }

    const int ntiles = (L + BK - 1) / BK;
    for (int kt = 0; kt < ntiles; ++kt) {
        const int k0 = kt * BK;
        __syncthreads();  // prev-iter consumers of sK/sV/sP done

        // cooperative load of K,V tile (zero-fill past L so 0*0 in PV)
        for (int idx = tid; idx < BK * (DIM / 4); idx += NT) {
            int r = idx >> 5, c4 = idx & 31;
            int krow = k0 + r;
            float4 kv4, vv4;
            if (krow < L) {
                kv4 = ((const float4*)(kb + (size_t)krow * DIM))[c4];
                vv4 = ((const float4*)(vb + (size_t)krow * DIM))[c4];
            } else {
                kv4 = make_float4(0.f, 0.f, 0.f, 0.f);
                vv4 = kv4;
            }
            ((float4*)(sK + r * QSTR))[c4] = kv4;
            ((float4*)(sV + r * QSTR))[c4] = vv4;
        }
        __syncthreads();

        // ---- phase 1: S = Q K^T (2q x 4k micro-tile, f32x2 packed) ----
        unsigned long long ae[2][4], ao[2][4];
#pragma unroll
        for (int i = 0; i < 2; ++i)
#pragma unroll
            for (int j = 0; j < 4; ++j) { ae[i][j] = 0ull; ao[i][j] = 0ull; }

        const float* qr0 = sQ + 2 * ty * QSTR;
        const float* qr1 = qr0 + QSTR;
#pragma unroll 4
        for (int d4 = 0; d4 < 32; ++d4) {
            ulonglong2 qa = *(const ulonglong2*)(qr0 + 4 * d4);
            ulonglong2 qc = *(const ulonglong2*)(qr1 + 4 * d4);
#pragma unroll
            for (int j = 0; j < 4; ++j) {
                ulonglong2 kk =
                    *(const ulonglong2*)(sK + (tx + 16 * j) * QSTR + 4 * d4);
                ae[0][j] = ffma2(qa.x, kk.x, ae[0][j]);
                ao[0][j] = ffma2(qa.y, kk.y, ao[0][j]);
                ae[1][j] = ffma2(qc.x, kk.x, ae[1][j]);
                ao[1][j] = ffma2(qc.y, kk.y, ao[1][j]);
            }
        }
        float s[2][4];
#pragma unroll
        for (int i = 0; i < 2; ++i)
#pragma unroll
            for (int j = 0; j < 4; ++j) {
                float2 e = unpack2(ae[i][j]);
                float2 o = unpack2(ao[i][j]);
                s[i][j] = (e.x + e.y) + (o.x + o.y);
            }
        // mask keys >= L (full overwrite, garbage-safe)
#pragma unroll
        for (int j = 0; j < 4; ++j) {
            if (k0 + tx + 16 * j >= L) { s[0][j] = NEGBIG; s[1][j] = NEGBIG; }
        }

        // ---- phase 2: online softmax (state duplicated across 16 tx lanes) ----
        float mt0 = fmaxf(fmaxf(s[0][0], s[0][1]), fmaxf(s[0][2], s[0][3]));
        float mt1 = fmaxf(fmaxf(s[1][0], s[1][1]), fmaxf(s[1][2], s[1][3]));
#pragma unroll
        for (int off = 1; off < 16; off <<= 1) {
            mt0 = fmaxf(mt0, __shfl_xor_sync(0xffffffffu, mt0, off));
            mt1 = fmaxf(mt1, __shfl_xor_sync(0xffffffffu, mt1, off));
        }
        float mn0 = fmaxf(mrun0, mt0), mn1 = fmaxf(mrun1, mt1);
        float c0 = __expf(mrun0 - mn0), c1 = __expf(mrun1 - mn1);
        mrun0 = mn0; mrun1 = mn1;
        float rs0 = 0.f, rs1 = 0.f;
#pragma unroll
        for (int j = 0; j < 4; ++j) {
            float p0 = __expf(s[0][j] - mn0);
            float p1 = __expf(s[1][j] - mn1);
            sP[(tx + 16 * j) * PSTR + 2 * ty]     = p0;
            sP[(tx + 16 * j) * PSTR + 2 * ty + 1] = p1;
            rs0 += p0; rs1 += p1;
        }
#pragma unroll
        for (int off = 1; off < 16; off <<= 1) {
            rs0 += __shfl_xor_sync(0xffffffffu, rs0, off);
            rs1 += __shfl_xor_sync(0xffffffffu, rs1, off);
        }
        lrun0 = lrun0 * c0 + rs0;
        lrun1 = lrun1 * c1 + rs1;
        if (tx == 0) {
            sC[2 * ty] = c0;     sC[2 * ty + 1] = c1;
            sL[2 * ty] = lrun0;  sL[2 * ty + 1] = lrun1;
        }
        __syncthreads();

        // ---- phase 3: O = O*c + P V (4q x 4d micro-tile) ----
        float4 cf = *(const float4*)(sC + 4 * qg);
        {
            unsigned long long pc;
            pc = pack2(cf.x); O2[0][0] = fmul2(O2[0][0], pc); O2[0][1] = fmul2(O2[0][1], pc);
            pc = pack2(cf.y); O2[1][0] = fmul2(O2[1][0], pc); O2[1][1] = fmul2(O2[1][1], pc);
            pc = pack2(cf.z); O2[2][0] = fmul2(O2[2][0], pc); O2[2][1] = fmul2(O2[2][1], pc);
            pc = pack2(cf.w); O2[3][0] = fmul2(O2[3][0], pc); O2[3][1] = fmul2(O2[3][1], pc);
        }
#pragma unroll 4
        for (int t = 0; t < BK; ++t) {
            float4 p4 = *(const float4*)(sP + t * PSTR + 4 * qg);     // broadcast
            ulonglong2 vv = *(const ulonglong2*)(sV + t * QSTR + 4 * dg);
            unsigned long long pk;
            pk = pack2(p4.x); O2[0][0] = ffma2(pk, vv.x, O2[0][0]); O2[0][1] = ffma2(pk, vv.y, O2[0][1]);
            pk = pack2(p4.y); O2[1][0] = ffma2(pk, vv.x, O2[1][0]); O2[1][1] = ffma2(pk, vv.y, O2[1][1]);
            pk = pack2(p4.z); O2[2][0] = ffma2(pk, vv.x, O2[2][0]); O2[2][1] = ffma2(pk, vv.y, O2[2][1]);
            pk = pack2(p4.w); O2[3][0] = ffma2(pk, vv.x, O2[3][0]); O2[3][1] = ffma2(pk, vv.y, O2[3][1]);
        }
    }
    __syncthreads();

    // epilogue: divide by denom; rows >= L get mean(V)
    float4 lf = *(const float4*)(sL + 4 * qg);
    float lv[4] = {lf.x, lf.y, lf.z, lf.w};
#pragma unroll
    for (int i = 0; i < 4; ++i) {
        int r = q0 + 4 * qg + i;
        float4 res;
        if (r >= L) {
            res = *(const float4*)(&g_meanv[b][4 * dg]);
        } else {
            float inv = 1.0f / lv[i];
            float2 a  = unpack2(O2[i][0]);
            float2 bb = unpack2(O2[i][1]);
            res = make_float4(a.x * inv, a.y * inv, bb.x * inv, bb.y * inv);
        }
        *((float4*)(ob + (size_t)r * DIM + 4 * dg)) = res;
    }
}

#define SMEM_BYTES ((BQ * QSTR + 2 * BK * QSTR + BK * PSTR + 2 * BQ) * 4)

extern "C" void kernel_launch(void* const* d_in, const int* in_sizes, int n_in,
                              void* d_out, int out_size) {
    const float* q  = (const float*)d_in[0];
    const float* k  = (const float*)d_in[1];
    const float* v  = (const float*)d_in[2];
    const int*   el = (const int*)d_in[3];
    float*       out = (float*)d_out;

    cudaFuncSetAttribute(attn_kernel,
                         cudaFuncAttributeMaxDynamicSharedMemorySize, SMEM_BYTES);

    meanv_partial_kernel<<<dim3(16, BATCH), 128>>>(v);
    meanv_reduce_kernel<<<BATCH, 128>>>();
    attn_kernel<<<dim3(SEQ / BQ, BATCH), NT, SMEM_BYTES>>>(q, k, v, el, out);
}

// round 2
// speedup vs baseline: 1.2926x; 1.2926x over previous
#include <cuda_runtime.h>
#include <cuda_bf16.h>

#define BATCH 8
#define SEQ   2048
#define DIM   128
#define BQ    32
#define BK    64
#define NT    256
#define QT    (SEQ / BQ)      // 64 q-tiles per batch
#define SPLITK 512            // keys per split CTA
#define MAXSPL (SEQ / SPLITK) // 4
#define QSTR  132             // padded row stride (floats) for Q/K/V tiles
#define PSTR  36              // padded row stride for transposed P tile
#define NEGBIG (-1e30f)

// ---- scratch (no allocations allowed) ----
__device__ float g_partial[BATCH][16][DIM];
__device__ float g_meanv[BATCH][DIM];
__device__ float g_pO[BATCH][QT][MAXSPL][BQ][DIM];   // unnormalized partial O
__device__ float g_pm[BATCH][QT][MAXSPL][BQ];        // partial row max
__device__ float g_pl[BATCH][QT][MAXSPL][BQ];        // partial row denom

// ---- packed f32x2 helpers ----
__device__ __forceinline__ unsigned long long ffma2(unsigned long long a,
                                                    unsigned long long b,
                                                    unsigned long long c) {
    unsigned long long d;
    asm("fma.rn.f32x2 %0, %1, %2, %3;" : "=l"(d) : "l"(a), "l"(b), "l"(c));
    return d;
}
__device__ __forceinline__ unsigned long long pack2(float x) {
    unsigned long long d;
    asm("mov.b64 %0, {%1, %1};" : "=l"(d) : "f"(x));
    return d;
}
__device__ __forceinline__ float2 unpack2(unsigned long long a) {
    float2 f;
    asm("mov.b64 {%0, %1}, %2;" : "=f"(f.x), "=f"(f.y) : "l"(a));
    return f;
}

// ---- flash attention over split key range, emits partials ----
__global__ void __launch_bounds__(NT, 2)
attn_kernel(const float* __restrict__ q, const float* __restrict__ k,
            const float* __restrict__ v, const int* __restrict__ elen) {
    extern __shared__ float smem[];
    float* sQ = smem;                    // BQ*QSTR
    float* sK = sQ + BQ * QSTR;          // BK*QSTR
    float* sV = sK + BK * QSTR;          // BK*QSTR
    float* sP = sV + BK * QSTR;          // BK*PSTR, transposed [t][q]
    float* sC = sP + BK * PSTR;          // BQ (rescale factor)
    float* sL = sC + BQ;                 // BQ (running denom)
    float* sM = sL + BQ;                 // BQ (running max)

    const int b    = blockIdx.y;
    const int qt   = blockIdx.x;
    const int spl  = blockIdx.z;
    const int q0   = qt * BQ;
    const int L    = elen[b];
    const int kbeg = spl * SPLITK;
    const int tid  = threadIdx.x;

    if (q0 >= L || kbeg >= L) return;   // combine kernel handles these rows
    const int kend = min(kbeg + SPLITK, L);

    const float* qb = q + (size_t)b * SEQ * DIM;
    const float* kb = k + (size_t)b * SEQ * DIM;
    const float* vb = v + (size_t)b * SEQ * DIM;

    // load Q tile, pre-scaled by 1/sqrt(D)
    const float scale = 0.08838834764831845f;
    for (int idx = tid; idx < BQ * (DIM / 4); idx += NT) {
        int r = idx >> 5, c4 = idx & 31;
        float4 val = ((const float4*)(qb + (size_t)(q0 + r) * DIM))[c4];
        val.x *= scale; val.y *= scale; val.z *= scale; val.w *= scale;
        ((float4*)(sQ + r * QSTR))[c4] = val;
    }

    const int ty = tid >> 4;   // phase1: q rows {2ty, 2ty+1}
    const int tx = tid & 15;   // phase1: k cols {tx+16j}
    const int qg = tid >> 5;   // phase3: q rows {4qg..4qg+3}
    const int dg = tid & 31;   // phase3: d cols {4dg..4dg+3}

    float mrun0 = NEGBIG, mrun1 = NEGBIG;
    float lrun0 = 0.f,    lrun1 = 0.f;
    unsigned long long O2[4][2];
#pragma unroll
    for (int i = 0; i < 4; ++i) { O2[i][0] = 0ull; O2[i][1] = 0ull; }

    const int ntiles = (kend - kbeg + BK - 1) / BK;
    for (int kt = 0; kt < ntiles; ++kt) {
        const int k0 = kbeg + kt * BK;
        __syncthreads();

        for (int idx = tid; idx < BK * (DIM / 4); idx += NT) {
            int r = idx >> 5, c4 = idx & 31;
            int krow = k0 + r;
            float4 kv4, vv4;
            if (krow < kend) {
                kv4 = ((const float4*)(kb + (size_t)krow * DIM))[c4];
                vv4 = ((const float4*)(vb + (size_t)krow * DIM))[c4];
            } else {
                kv4 = make_float4(0.f, 0.f, 0.f, 0.f);
                vv4 = kv4;
            }
            ((float4*)(sK + r * QSTR))[c4] = kv4;
            ((float4*)(sV + r * QSTR))[c4] = vv4;
        }
        __syncthreads();

        // ---- phase 1: S = Q K^T ----
        unsigned long long ae[2][4], ao[2][4];
#pragma unroll
        for (int i = 0; i < 2; ++i)
#pragma unroll
            for (int j = 0; j < 4; ++j) { ae[i][j] = 0ull; ao[i][j] = 0ull; }

        const float* qr0 = sQ + 2 * ty * QSTR;
        const float* qr1 = qr0 + QSTR;
#pragma unroll 4
        for (int d4 = 0; d4 < 32; ++d4) {
            ulonglong2 qa = *(const ulonglong2*)(qr0 + 4 * d4);
            ulonglong2 qc = *(const ulonglong2*)(qr1 + 4 * d4);
#pragma unroll
            for (int j = 0; j < 4; ++j) {
                ulonglong2 kk =
                    *(const ulonglong2*)(sK + (tx + 16 * j) * QSTR + 4 * d4);
                ae[0][j] = ffma2(qa.x, kk.x, ae[0][j]);
                ao[0][j] = ffma2(qa.y, kk.y, ao[0][j]);
                ae[1][j] = ffma2(qc.x, kk.x, ae[1][j]);
                ao[1][j] = ffma2(qc.y, kk.y, ao[1][j]);
            }
        }
        float s[2][4];
#pragma unroll
        for (int i = 0; i < 2; ++i)
#pragma unroll
            for (int j = 0; j < 4; ++j) {
                float2 e = unpack2(ae[i][j]);
                float2 o = unpack2(ao[i][j]);
                s[i][j] = (e.x + e.y) + (o.x + o.y);
            }
#pragma unroll
        for (int j = 0; j < 4; ++j) {
            if (k0 + tx + 16 * j >= kend) { s[0][j] = NEGBIG; s[1][j] = NEGBIG; }
        }

        // ---- phase 2: online softmax ----
        float mt0 = fmaxf(fmaxf(s[0][0], s[0][1]), fmaxf(s[0][2], s[0][3]));
        float mt1 = fmaxf(fmaxf(s[1][0], s[1][1]), fmaxf(s[1][2], s[1][3]));
#pragma unroll
        for (int off = 1; off < 16; off <<= 1) {
            mt0 = fmaxf(mt0, __shfl_xor_sync(0xffffffffu, mt0, off));
            mt1 = fmaxf(mt1, __shfl_xor_sync(0xffffffffu, mt1, off));
        }
        float mn0 = fmaxf(mrun0, mt0), mn1 = fmaxf(mrun1, mt1);
        float c0 = __expf(mrun0 - mn0), c1 = __expf(mrun1 - mn1);
        mrun0 = mn0; mrun1 = mn1;
        float rs0 = 0.f, rs1 = 0.f;
#pragma unroll
        for (int j = 0; j < 4; ++j) {
            float p0 = __expf(s[0][j] - mn0);
            float p1 = __expf(s[1][j] - mn1);
            sP[(tx + 16 * j) * PSTR + 2 * ty]     = p0;
            sP[(tx + 16 * j) * PSTR + 2 * ty + 1] = p1;
            rs0 += p0; rs1 += p1;
        }
#pragma unroll
        for (int off = 1; off < 16; off <<= 1) {
            rs0 += __shfl_xor_sync(0xffffffffu, rs0, off);
            rs1 += __shfl_xor_sync(0xffffffffu, rs1, off);
        }
        lrun0 = lrun0 * c0 + rs0;
        lrun1 = lrun1 * c1 + rs1;
        if (tx == 0) {
            sC[2 * ty] = c0;     sC[2 * ty + 1] = c1;
            sL[2 * ty] = lrun0;  sL[2 * ty + 1] = lrun1;
            sM[2 * ty] = mrun0;  sM[2 * ty + 1] = mrun1;
        }
        __syncthreads();

        // ---- phase 3: O = O*c + P V ----
        float4 cf = *(const float4*)(sC + 4 * qg);
        {
            unsigned long long pc;
            pc = pack2(cf.x); O2[0][0] = ffma2(O2[0][0], pc, 0ull); O2[0][1] = ffma2(O2[0][1], pc, 0ull);
            pc = pack2(cf.y); O2[1][0] = ffma2(O2[1][0], pc, 0ull); O2[1][1] = ffma2(O2[1][1], pc, 0ull);
            pc = pack2(cf.z); O2[2][0] = ffma2(O2[2][0], pc, 0ull); O2[2][1] = ffma2(O2[2][1], pc, 0ull);
            pc = pack2(cf.w); O2[3][0] = ffma2(O2[3][0], pc, 0ull); O2[3][1] = ffma2(O2[3][1], pc, 0ull);
        }
#pragma unroll 4
        for (int t = 0; t < BK; ++t) {
            float4 p4 = *(const float4*)(sP + t * PSTR + 4 * qg);     // broadcast
            ulonglong2 vv = *(const ulonglong2*)(sV + t * QSTR + 4 * dg);
            unsigned long long pk;
            pk = pack2(p4.x); O2[0][0] = ffma2(pk, vv.x, O2[0][0]); O2[0][1] = ffma2(pk, vv.y, O2[0][1]);
            pk = pack2(p4.y); O2[1][0] = ffma2(pk, vv.x, O2[1][0]); O2[1][1] = ffma2(pk, vv.y, O2[1][1]);
            pk = pack2(p4.z); O2[2][0] = ffma2(pk, vv.x, O2[2][0]); O2[2][1] = ffma2(pk, vv.y, O2[2][1]);
            pk = pack2(p4.w); O2[3][0] = ffma2(pk, vv.x, O2[3][0]); O2[3][1] = ffma2(pk, vv.y, O2[3][1]);
        }
    }
    __syncthreads();

    // epilogue: write unnormalized partials + (m, l)
    float4 lf = *(const float4*)(sL + 4 * qg);
    float4 mf = *(const float4*)(sM + 4 * qg);
    float lv[4] = {lf.x, lf.y, lf.z, lf.w};
    float mv4[4] = {mf.x, mf.y, mf.z, mf.w};
    float* baseO = &g_pO[b][qt][spl][0][0];
#pragma unroll
    for (int i = 0; i < 4; ++i) {
        int r = 4 * qg + i;
        float2 a  = unpack2(O2[i][0]);
        float2 bb = unpack2(O2[i][1]);
        *((float4*)(baseO + (size_t)r * DIM + 4 * dg)) =
            make_float4(a.x, a.y, bb.x, bb.y);
        if (dg == 0) {
            g_pm[b][qt][spl][r] = mv4[i];
            g_pl[b][qt][spl][r] = lv[i];
        }
    }
}

// ---- mean-of-V ----
__global__ void meanv_partial_kernel(const float* __restrict__ v) {
    int b = blockIdx.y, c = blockIdx.x, d = threadIdx.x;
    const float* vp = v + ((size_t)b * SEQ + (size_t)c * 128) * DIM + d;
    float s = 0.f;
#pragma unroll 8
    for (int t = 0; t < 128; ++t) s += vp[(size_t)t * DIM];
    g_partial[b][c][d] = s;
}

__global__ void meanv_reduce_kernel() {
    int b = blockIdx.x, d = threadIdx.x;
    float s = 0.f;
#pragma unroll
    for (int c = 0; c < 16; ++c) s += g_partial[b][c][d];
    g_meanv[b][d] = s * (1.0f / SEQ);
}

// ---- combine partials, write final output ----
__global__ void __launch_bounds__(NT)
combine_kernel(const int* __restrict__ elen, float* __restrict__ out) {
    const int b   = blockIdx.y;
    const int qt  = blockIdx.x;
    const int tid = threadIdx.x;
    const int r    = tid >> 3;        // 0..31 row in tile
    const int dgrp = tid & 7;         // 16-dim group
    const int row  = qt * BQ + r;
    const int L    = elen[b];

    float* op = out + ((size_t)b * SEQ + row) * DIM + dgrp * 16;

    if (row >= L) {   // uniform softmax -> mean(V)
        const float4* mv = (const float4*)(&g_meanv[b][dgrp * 16]);
#pragma unroll
        for (int j = 0; j < 4; ++j) ((float4*)op)[j] = mv[j];
        return;
    }

    const int nspl = (L + SPLITK - 1) >> 9;
    float mmax = NEGBIG;
    for (int s = 0; s < nspl; ++s) mmax = fmaxf(mmax, g_pm[b][qt][s][r]);

    float acc[16];
#pragma unroll
    for (int j = 0; j < 16; ++j) acc[j] = 0.f;
    float lsum = 0.f;

    for (int s = 0; s < nspl; ++s) {
        float w = __expf(g_pm[b][qt][s][r] - mmax);
        lsum += w * g_pl[b][qt][s][r];
        const float4* po = (const float4*)(&g_pO[b][qt][s][r][dgrp * 16]);
#pragma unroll
        for (int j = 0; j < 4; ++j) {
            float4 t = po[j];
            acc[4 * j + 0] += w * t.x;
            acc[4 * j + 1] += w * t.y;
            acc[4 * j + 2] += w * t.z;
            acc[4 * j + 3] += w * t.w;
        }
    }
    float inv = 1.0f / lsum;
#pragma unroll
    for (int j = 0; j < 4; ++j) {
        ((float4*)op)[j] = make_float4(acc[4 * j + 0] * inv, acc[4 * j + 1] * inv,
                                       acc[4 * j + 2] * inv, acc[4 * j + 3] * inv);
    }
}

#define SMEM_BYTES ((BQ * QSTR + 2 * BK * QSTR + BK * PSTR + 3 * BQ) * 4)

extern "C" void kernel_launch(void* const* d_in, const int* in_sizes, int n_in,
                              void* d_out, int out_size) {
    const float* q  = (const float*)d_in[0];
    const float* k  = (const float*)d_in[1];
    const float* v  = (const float*)d_in[2];
    const int*   el = (const int*)d_in[3];
    float*       out = (float*)d_out;

    cudaFuncSetAttribute(attn_kernel,
                         cudaFuncAttributeMaxDynamicSharedMemorySize, SMEM_BYTES);

    // attn first (so ncu -s 5 -c 1 lands on it), meanv concurrent-agnostic,
    // combine last (reads partials + meanv, writes all outputs).
    attn_kernel<<<dim3(QT, BATCH, MAXSPL), NT, SMEM_BYTES>>>(q, k, v, el);
    meanv_partial_kernel<<<dim3(16, BATCH), 128>>>(v);
    meanv_reduce_kernel<<<BATCH, 128>>>();
    combine_kernel<<<dim3(QT, BATCH), NT>>>(el, out);
}

// round 6
// speedup vs baseline: 2.5239x; 1.9525x over previous
#include <cuda_runtime.h>
#include <cuda_bf16.h>
#include <cstdint>

#define BATCH 8
#define SEQ   2048
#define DIM   128
#define BQ    128              // queries per CTA (8 warps x 16 rows)
#define BK    64               // keys per inner tile
#define NT    256
#define QT    (SEQ / BQ)       // 16
#define SPLITK 512
#define MAXSPL (SEQ / SPLITK)  // 4

// strides in 32-bit words
#define KFSTR 132   // fp32 K staging rows (also Q staging)
#define KBSTR 68    // bf16-pair K rows (68 mod 32 = 4 -> banks 4g+qd distinct)
#define VSTR  136   // fp32 V rows (8k+n distinct banks)
#define PSTR  68    // per-warp P rows

// smem word offsets
#define KF0w 0                       // 64*132
#define KF1w (64 * KFSTR)            // second stage (Q staging rows 64..127)
#define KHIw (2 * 64 * KFSTR)        // 16896: 64*68 bf16-pair hi
#define KLOw (KHIw + 64 * KBSTR)     // 21248: 64*68 lo
#define VS0w (KLOw + 64 * KBSTR)     // 25600
#define VS1w (VS0w + 64 * VSTR)      // 34304
#define Pw   (VS0w + 2 * 64 * VSTR)  // 43008
#define SMEM_WORDS (Pw + 8 * 16 * PSTR)   // 51712
#define SMEM_BYTES (SMEM_WORDS * 4)       // 206848

// ---- scratch (no allocations allowed) ----
__device__ float g_partial[BATCH][16][DIM];
__device__ float g_meanv[BATCH][DIM];
__device__ float g_pO[BATCH][QT][MAXSPL][BQ][DIM];
__device__ float g_pl[BATCH][QT][MAXSPL][BQ];

// ---- helpers ----
__device__ __forceinline__ uint32_t smem_u32(const void* p) {
    uint32_t a;
    asm("{ .reg .u64 t; cvta.to.shared.u64 t, %1; cvt.u32.u64 %0, t; }"
        : "=r"(a) : "l"(p));
    return a;
}
__device__ __forceinline__ void mma_bf16(float* c, const uint32_t* a,
                                         uint32_t b0, uint32_t b1) {
    asm volatile(
        "mma.sync.aligned.m16n8k16.row.col.f32.bf16.bf16.f32 "
        "{%0,%1,%2,%3}, {%4,%5,%6,%7}, {%8,%9}, {%0,%1,%2,%3};"
        : "+f"(c[0]), "+f"(c[1]), "+f"(c[2]), "+f"(c[3])
        : "r"(a[0]), "r"(a[1]), "r"(a[2]), "r"(a[3]), "r"(b0), "r"(b1));
}
__device__ __forceinline__ void mma_tf32(float* c, const uint32_t* a,
                                         uint32_t b0, uint32_t b1) {
    asm volatile(
        "mma.sync.aligned.m16n8k8.row.col.f32.tf32.tf32.f32 "
        "{%0,%1,%2,%3}, {%4,%5,%6,%7}, {%8,%9}, {%0,%1,%2,%3};"
        : "+f"(c[0]), "+f"(c[1]), "+f"(c[2]), "+f"(c[3])
        : "r"(a[0]), "r"(a[1]), "r"(a[2]), "r"(a[3]), "r"(b0), "r"(b1));
}
__device__ __forceinline__ float tf32_round(float x) {
    uint32_t u;
    asm("cvt.rna.tf32.f32 %0, %1;" : "=r"(u) : "f"(x));
    return __uint_as_float(u);
}
// pack (x0 -> lo, x1 -> hi) into bf16x2 hi-part h and residual-part l
__device__ __forceinline__ void pack_hl(float x0, float x1,
                                        uint32_t& h, uint32_t& l) {
    asm("cvt.rn.bf16x2.f32 %0, %1, %2;" : "=r"(h) : "f"(x1), "f"(x0));
    float r0 = x0 - __uint_as_float(h << 16);
    float r1 = x1 - __uint_as_float(h & 0xFFFF0000u);
    asm("cvt.rn.bf16x2.f32 %0, %1, %2;" : "=r"(l) : "f"(r1), "f"(r0));
}
#define CP_ASYNC16(dst, src, sz) \
    asm volatile("cp.async.ca.shared.global [%0], [%1], 16, %2;" \
                 :: "r"(dst), "l"(src), "r"(sz) : "memory")
#define CP_COMMIT() asm volatile("cp.async.commit_group;" ::: "memory")

// ---- bf16x3 QK / tf32 PV flash attention (no-max softmax), split-K ----
__global__ void __launch_bounds__(NT, 1)
attn_kernel(const float* __restrict__ q, const float* __restrict__ k,
            const float* __restrict__ v, const int* __restrict__ elen,
            int spl_base) {
    extern __shared__ float sm[];
    const int b    = blockIdx.y;
    const int qt   = blockIdx.x;
    const int spl  = spl_base + 2 * blockIdx.z;
    const int q0   = qt * BQ;
    const int L    = elen[b];
    const int kbeg = spl * SPLITK;
    const int tid  = threadIdx.x;
    const int wid  = tid >> 5;
    const int lane = tid & 31;
    const int g    = lane >> 2;
    const int qd   = lane & 3;

    if (q0 >= L || kbeg >= L) return;
    const int kend = min(kbeg + SPLITK, L);
    const int ntiles = (kend - kbeg + BK - 1) / BK;

    const uint32_t sbase = smem_u32(sm);
    const float* qb = q + ((size_t)b * SEQ + q0) * DIM;
    const float* kb = k + (size_t)b * SEQ * DIM;
    const float* vb = v + (size_t)b * SEQ * DIM;

    // ---- stage Q (scaled) through Kf32 staging (rows 0..127, stride 132)
    const float scale = 0.08838834764831845f;
#pragma unroll
    for (int i = 0; i < 16; ++i) {
        int idx = tid + i * NT;
        int r = idx >> 5, c4 = idx & 31;
        float4 t = ((const float4*)(qb + (size_t)r * DIM))[c4];
        t.x *= scale; t.y *= scale; t.z *= scale; t.w *= scale;
        *(float4*)&sm[r * KFSTR + c4 * 4] = t;
    }
    __syncthreads();

    // ---- build resident bf16 hi/lo Q fragments (8 k16 chunks)
    uint32_t Qh[8][4], Ql[8][4];
    {
        const int r0 = wid * 16 + g;
        const float* row0 = &sm[r0 * KFSTR];
        const float* row1 = &sm[(r0 + 8) * KFSTR];
#pragma unroll
        for (int kc = 0; kc < 8; ++kc) {
            int c = kc * 16 + 2 * qd;
            pack_hl(row0[c],     row0[c + 1], Qh[kc][0], Ql[kc][0]);
            pack_hl(row1[c],     row1[c + 1], Qh[kc][1], Ql[kc][1]);
            pack_hl(row0[c + 8], row0[c + 9], Qh[kc][2], Ql[kc][2]);
            pack_hl(row1[c + 8], row1[c + 9], Qh[kc][3], Ql[kc][3]);
        }
    }
    __syncthreads();

    // ---- cp.async tile loader (zero-fill past kend)
    auto load_tile = [&](int st, int k0) {
        uint32_t kwb = sbase + (st ? KF1w : KF0w) * 4;
        uint32_t vwb = sbase + (st ? VS1w : VS0w) * 4;
#pragma unroll
        for (int i = 0; i < 8; ++i) {
            int idx = tid + i * NT;
            int r = idx >> 5, c4 = idx & 31;
            int gr = k0 + r;
            int sz = (gr < kend) ? 16 : 0;
            gr = min(gr, SEQ - 1);
            CP_ASYNC16(kwb + (uint32_t)(r * KFSTR + c4 * 4) * 4,
                       kb + (size_t)gr * DIM + c4 * 4, sz);
            CP_ASYNC16(vwb + (uint32_t)(r * VSTR + c4 * 4) * 4,
                       vb + (size_t)gr * DIM + c4 * 4, sz);
        }
    };

    load_tile(0, kbeg);
    CP_COMMIT();

    float o[16][4];
#pragma unroll
    for (int nc = 0; nc < 16; ++nc)
#pragma unroll
        for (int i = 0; i < 4; ++i) o[nc][i] = 0.f;
    float lsum0 = 0.f, lsum1 = 0.f;

    float* sp = &sm[Pw + wid * 16 * PSTR];
    const uint32_t* khi = (const uint32_t*)&sm[KHIw];
    const uint32_t* klo = (const uint32_t*)&sm[KLOw];

    for (int kt = 0; kt < ntiles; ++kt) {
        const int k0 = kbeg + kt * BK;
        const int st = kt & 1;
        if (kt + 1 < ntiles) {
            load_tile((kt + 1) & 1, k0 + BK);
            CP_COMMIT();
            asm volatile("cp.async.wait_group 1;" ::: "memory");
        } else {
            asm volatile("cp.async.wait_group 0;" ::: "memory");
        }
        __syncthreads();

        // ---- convert K tile fp32 -> bf16 hi/lo (single-buffered, safe: all
        // warps passed last iter's MMA1 before the loop-end barrier)
        {
            const float* kf = &sm[st ? KF1w : KF0w];
            uint32_t* dh = (uint32_t*)&sm[KHIw];
            uint32_t* dl = (uint32_t*)&sm[KLOw];
#pragma unroll
            for (int i = 0; i < 8; ++i) {
                int idx = tid + i * NT;
                int r = idx >> 5, c4 = idx & 31;
                float4 t = *(const float4*)&kf[r * KFSTR + c4 * 4];
                uint32_t h01, l01, h23, l23;
                pack_hl(t.x, t.y, h01, l01);
                pack_hl(t.z, t.w, h23, l23);
                uint2* ph = (uint2*)&dh[r * KBSTR + 2 * c4];
                uint2* pl = (uint2*)&dl[r * KBSTR + 2 * c4];
                *ph = make_uint2(h01, h23);
                *pl = make_uint2(l01, l23);
            }
        }
        __syncthreads();

        const float* sv = &sm[st ? VS1w : VS0w];

        // ---- QK^T: S[16 x 64] per warp, bf16x3
        float s[8][4];
#pragma unroll
        for (int nc = 0; nc < 8; ++nc)
#pragma unroll
            for (int i = 0; i < 4; ++i) s[nc][i] = 0.f;
#pragma unroll
        for (int kc = 0; kc < 8; ++kc) {
#pragma unroll
            for (int nc = 0; nc < 8; ++nc) {
                int base = (nc * 8 + g) * KBSTR + kc * 8 + qd;
                uint32_t bh0 = khi[base], bh1 = khi[base + 4];
                uint32_t bl0 = klo[base], bl1 = klo[base + 4];
                mma_bf16(s[nc], Qh[kc], bh0, bh1);
                mma_bf16(s[nc], Qh[kc], bl0, bl1);
                mma_bf16(s[nc], Ql[kc], bh0, bh1);
            }
        }

        // ---- mask + exp + tf32-round; P -> per-warp smem; l accumulation
#pragma unroll
        for (int nc = 0; nc < 8; ++nc) {
            int c0 = k0 + nc * 8 + 2 * qd;
            bool v0 = c0 < kend, v1 = c0 + 1 < kend;
            float p0 = v0 ? tf32_round(__expf(s[nc][0])) : 0.f;
            float p1 = v1 ? tf32_round(__expf(s[nc][1])) : 0.f;
            float p2 = v0 ? tf32_round(__expf(s[nc][2])) : 0.f;
            float p3 = v1 ? tf32_round(__expf(s[nc][3])) : 0.f;
            lsum0 += p0 + p1;
            lsum1 += p2 + p3;
            *(float2*)&sp[g * PSTR + nc * 8 + 2 * qd]       = make_float2(p0, p1);
            *(float2*)&sp[(g + 8) * PSTR + nc * 8 + 2 * qd] = make_float2(p2, p3);
        }
        __syncwarp();

        // ---- PV: O[16 x 128] += P[16 x 64] V[64 x 128]  (tf32)
#pragma unroll
        for (int kc = 0; kc < 8; ++kc) {
            uint32_t A[4];
            A[0] = __float_as_uint(sp[g * PSTR + kc * 8 + qd]);
            A[1] = __float_as_uint(sp[(g + 8) * PSTR + kc * 8 + qd]);
            A[2] = __float_as_uint(sp[g * PSTR + kc * 8 + 4 + qd]);
            A[3] = __float_as_uint(sp[(g + 8) * PSTR + kc * 8 + 4 + qd]);
#pragma unroll
            for (int nc = 0; nc < 16; ++nc) {
                uint32_t b0 = __float_as_uint(sv[(kc * 8 + qd) * VSTR + nc * 8 + g]);
                uint32_t b1 = __float_as_uint(sv[(kc * 8 + 4 + qd) * VSTR + nc * 8 + g]);
                mma_tf32(o[nc], A, b0, b1);
            }
        }
        __syncthreads();
    }

    // ---- epilogue: write unnormalized O + l
    lsum0 += __shfl_xor_sync(0xffffffffu, lsum0, 1);
    lsum0 += __shfl_xor_sync(0xffffffffu, lsum0, 2);
    lsum1 += __shfl_xor_sync(0xffffffffu, lsum1, 1);
    lsum1 += __shfl_xor_sync(0xffffffffu, lsum1, 2);

    const int r0 = wid * 16 + g;
    float* o0 = &g_pO[b][qt][spl][r0][0];
    float* o1 = &g_pO[b][qt][spl][r0 + 8][0];
#pragma unroll
    for (int nc = 0; nc < 16; ++nc) {
        *(float2*)&o0[nc * 8 + 2 * qd] = make_float2(o[nc][0], o[nc][1]);
        *(float2*)&o1[nc * 8 + 2 * qd] = make_float2(o[nc][2], o[nc][3]);
    }
    if (qd == 0) {
        g_pl[b][qt][spl][r0]     = lsum0;
        g_pl[b][qt][spl][r0 + 8] = lsum1;
    }
}

// ---- mean-of-V ----
__global__ void meanv_partial_kernel(const float* __restrict__ v) {
    __shared__ float4 red[8][32];
    int b = blockIdx.y, ch = blockIdx.x;
    int c4 = threadIdx.x & 31, rg = threadIdx.x >> 5;
    const float4* vp = (const float4*)(v + ((size_t)b * SEQ + (size_t)ch * 128) * DIM);
    float4 acc = make_float4(0.f, 0.f, 0.f, 0.f);
    for (int r = rg; r < 128; r += 8) {
        float4 t = vp[(size_t)r * 32 + c4];
        acc.x += t.x; acc.y += t.y; acc.z += t.z; acc.w += t.w;
    }
    red[rg][c4] = acc;
    __syncthreads();
    if (rg == 0) {
        float4 s = make_float4(0.f, 0.f, 0.f, 0.f);
#pragma unroll
        for (int gg = 0; gg < 8; ++gg) {
            float4 t = red[gg][c4];
            s.x += t.x; s.y += t.y; s.z += t.z; s.w += t.w;
        }
        ((float4*)&g_partial[b][ch][0])[c4] = s;
    }
}

__global__ void meanv_reduce_kernel() {
    int b = blockIdx.x, d = threadIdx.x;
    float s = 0.f;
#pragma unroll
    for (int c = 0; c < 16; ++c) s += g_partial[b][c][d];
    g_meanv[b][d] = s * (1.0f / SEQ);
}

// ---- combine: plain-sum split partials, normalize; meanv for rows >= L ----
__global__ void __launch_bounds__(NT)
combine_kernel(const int* __restrict__ elen, float* __restrict__ out) {
    const int b   = blockIdx.y;
    const int qt  = blockIdx.x;
    const int tid = threadIdx.x;
    const int r     = tid >> 1;
    const int dhalf = (tid & 1) * 16;
    const int row   = qt * BQ + r;
    const int L     = elen[b];

    float4* op = (float4*)(out + ((size_t)b * SEQ + row) * DIM) + dhalf;

    if (row >= L) {
        const float4* mv = (const float4*)(&g_meanv[b][0]) + dhalf;
#pragma unroll
        for (int j = 0; j < 16; ++j) op[j] = mv[j];
        return;
    }

    const int nspl = (L + SPLITK - 1) / SPLITK;
    float lsum = 0.f;
    float4 acc[16];
#pragma unroll
    for (int j = 0; j < 16; ++j) acc[j] = make_float4(0.f, 0.f, 0.f, 0.f);

    for (int s = 0; s < nspl; ++s) {
        lsum += g_pl[b][qt][s][r];
        const float4* po = (const float4*)(&g_pO[b][qt][s][r][0]) + dhalf;
#pragma unroll
        for (int j = 0; j < 16; ++j) {
            float4 t = po[j];
            acc[j].x += t.x; acc[j].y += t.y; acc[j].z += t.z; acc[j].w += t.w;
        }
    }
    float inv = 1.0f / lsum;
#pragma unroll
    for (int j = 0; j < 16; ++j)
        op[j] = make_float4(acc[j].x * inv, acc[j].y * inv,
                            acc[j].z * inv, acc[j].w * inv);
}

extern "C" void kernel_launch(void* const* d_in, const int* in_sizes, int n_in,
                              void* d_out, int out_size) {
    const float* q  = (const float*)d_in[0];
    const float* k  = (const float*)d_in[1];
    const float* v  = (const float*)d_in[2];
    const int*   el = (const int*)d_in[3];
    float*       out = (float*)d_out;

    cudaFuncSetAttribute(attn_kernel,
                         cudaFuncAttributeMaxDynamicSharedMemorySize, SMEM_BYTES);

    // 5 launches per replay -> ncu -s 5 -c 1 lands on an attn instance
    attn_kernel<<<dim3(QT, BATCH, 2), NT, SMEM_BYTES>>>(q, k, v, el, 0);
    attn_kernel<<<dim3(QT, BATCH, 2), NT, SMEM_BYTES>>>(q, k, v, el, 1);
    meanv_partial_kernel<<<dim3(16, BATCH), NT>>>(v);
    meanv_reduce_kernel<<<BATCH, DIM>>>();
    combine_kernel<<<dim3(QT, BATCH), NT>>>(el, out);
}